// round 5
// baseline (speedup 1.0000x reference)
#include <cuda_runtime.h>
#include <cuda_bf16.h>

#define NN 100000
#define EE 800000
#define HH 128
#define GG 64
#define LL 4

typedef unsigned int u32;
typedef unsigned short u16;

// ------------------ static device scratch ------------------
__device__ float g_h[(size_t)NN * HH];
__device__ float g_z[(size_t)NN * HH];
__device__ int   g_deg[NN];
__device__ int   g_rowptr[NN + 1];
__device__ int   g_cur[NN];
__device__ int   g_colidx[2 * EE];
__device__ int   g_bsum[128];
__device__ int   g_boff[128];
__device__ float g_colsum[HH];
__device__ float g_colsq[HH];
__device__ __align__(16) float g_bnscale[HH];
__device__ __align__(16) float g_bnshift[HH];
__device__ float g_pool[GG * HH];
__device__ float g_cnt[GG];
__device__ __align__(16) u16 g_wthi[9 * HH * HH];  // transposed [n][k] bf16 hi
__device__ __align__(16) u16 g_wtlo[9 * HH * HH];  // bf16 lo residual

// ------------------ PTX helpers ------------------
__device__ __forceinline__ u32 smem_u32(const void* p) {
    u32 a;
    asm("{ .reg .u64 t; cvta.to.shared.u64 t, %1; cvt.u32.u64 %0, t; }" : "=r"(a) : "l"(p));
    return a;
}
__device__ __forceinline__ void ldm4(u32 r[4], u32 addr) {
    asm volatile("ldmatrix.sync.aligned.m8n8.x4.shared.b16 {%0,%1,%2,%3}, [%4];"
                 : "=r"(r[0]), "=r"(r[1]), "=r"(r[2]), "=r"(r[3]) : "r"(addr));
}
__device__ __forceinline__ void mma16816(float* c, const u32 a[4], u32 b0, u32 b1) {
    asm volatile(
        "mma.sync.aligned.m16n8k16.row.col.f32.bf16.bf16.f32 "
        "{%0,%1,%2,%3}, {%4,%5,%6,%7}, {%8,%9}, {%0,%1,%2,%3};"
        : "+f"(c[0]), "+f"(c[1]), "+f"(c[2]), "+f"(c[3])
        : "r"(a[0]), "r"(a[1]), "r"(a[2]), "r"(a[3]), "r"(b0), "r"(b1));
}
__device__ __forceinline__ u32 packbf2(float x, float y) {
    __nv_bfloat162 t = __floats2bfloat162_rn(x, y);
    return *(u32*)&t;
}

// ================== half-K GEMM (MODE 0 / MODE 2), unchanged from R4 ==================
constexpr int SMEM_HM = 17280 * 4;   // 69120 B
constexpr int F_BIAS = 16896, F_LNG = 17024, F_LNB = 17152;

template <int MODE>
__global__ void __launch_bounds__(256, 2) gemm_hmma(
    const float* __restrict__ A, const u16* __restrict__ Whi, const u16* __restrict__ Wlo,
    const float* __restrict__ bias, float* __restrict__ C,
    const float* __restrict__ lng, const float* __restrict__ lnb)
{
    extern __shared__ float sm[];
    const u32 sb = smem_u32(sm);
    const int tid = threadIdx.x;
    const int lane = tid & 31, wid = tid >> 5;
    const int row0 = blockIdx.x * 128;

    if (tid < 128) {
        sm[F_BIAS + tid] = __ldg(bias + tid);
        if (MODE == 2) { sm[F_LNG + tid] = __ldg(lng + tid); sm[F_LNB + tid] = __ldg(lnb + tid); }
    }

    float c[16][4];
#pragma unroll
    for (int n = 0; n < 16; n++)
#pragma unroll
        for (int j = 0; j < 4; j++) c[n][j] = 0.f;

    for (int h = 0; h < 2; h++) {
#pragma unroll
        for (int i = 0; i < 4; i++) {
            int f = i * 256 + tid;
            int n = f >> 3, q = f & 7;
            uint4 vh = __ldg((const uint4*)(Whi + (size_t)n * HH + h * 64) + q);
            uint4 vl = __ldg((const uint4*)(Wlo + (size_t)n * HH + h * 64) + q);
            u32 off = (u32)(n * 128 + ((q ^ (n & 7)) << 4));
            *(uint4*)((char*)sm + 32768 + off) = vh;
            *(uint4*)((char*)sm + 49152 + off) = vl;
        }
#pragma unroll
        for (int i = 0; i < 8; i++) {
            int f = i * 256 + tid;
            int r = f >> 4, c4 = f & 15;
            int row = row0 + r;
            float4 v = make_float4(0.f, 0.f, 0.f, 0.f);
            if (row < NN) v = __ldg((const float4*)(A + (size_t)row * HH + h * 64) + c4);
            if (MODE == 2) {
                float4 sc = ((const float4*)g_bnscale)[h * 16 + c4];
                float4 sh = ((const float4*)g_bnshift)[h * 16 + c4];
                v.x = fmaxf(fmaf(v.x, sc.x, sh.x), 0.f);
                v.y = fmaxf(fmaf(v.y, sc.y, sh.y), 0.f);
                v.z = fmaxf(fmaf(v.z, sc.z, sh.z), 0.f);
                v.w = fmaxf(fmaf(v.w, sc.w, sh.w), 0.f);
            }
            float hx = __bfloat162float(__float2bfloat16_rn(v.x));
            float hy = __bfloat162float(__float2bfloat16_rn(v.y));
            float hz = __bfloat162float(__float2bfloat16_rn(v.z));
            float hw = __bfloat162float(__float2bfloat16_rn(v.w));
            u32 off = (u32)(r * 128 + (((c4 >> 1) ^ (r & 7)) << 4) + (c4 & 1) * 8);
            *(uint2*)((char*)sm + off) = make_uint2(packbf2(v.x, v.y), packbf2(v.z, v.w));
            *(uint2*)((char*)sm + 16384 + off) =
                make_uint2(packbf2(v.x - hx, v.y - hy), packbf2(v.z - hz, v.w - hw));
        }
        __syncthreads();

        const int ar = (wid << 4) + (lane & 7) + (lane & 8);
        const int bq = ((lane >> 4) << 3) + (lane & 7);
#pragma unroll
        for (int s = 0; s < 4; s++) {
            int ach = 2 * s + (lane >> 4);
            u32 aoff = (u32)(ar * 128 + ((ach ^ (ar & 7)) << 4));
            u32 ah[4], al[4];
            ldm4(ah, sb + aoff);
            ldm4(al, sb + 16384 + aoff);
            int bch = 2 * s + ((lane >> 3) & 1);
#pragma unroll
            for (int n2 = 0; n2 < 8; n2++) {
                int bn = (n2 << 4) + bq;
                u32 boff = (u32)(bn * 128 + ((bch ^ (bn & 7)) << 4));
                u32 bh[4], bl[4];
                ldm4(bh, sb + 32768 + boff);
                ldm4(bl, sb + 49152 + boff);
                mma16816(c[2 * n2],     ah, bh[0], bh[1]);
                mma16816(c[2 * n2],     ah, bl[0], bl[1]);
                mma16816(c[2 * n2],     al, bh[0], bh[1]);
                mma16816(c[2 * n2 + 1], ah, bh[2], bh[3]);
                mma16816(c[2 * n2 + 1], ah, bl[2], bl[3]);
                mma16816(c[2 * n2 + 1], al, bh[2], bh[3]);
            }
        }
        __syncthreads();
    }

    {
        const int r0s = (wid << 4) + (lane >> 2);
#pragma unroll
        for (int n = 0; n < 16; n++) {
            int col = n * 8 + (lane & 3) * 2;
            float b0 = sm[F_BIAS + col], b1 = sm[F_BIAS + col + 1];
            *(float2*)&sm[r0s * 132 + col] = make_float2(c[n][0] + b0, c[n][1] + b1);
            *(float2*)&sm[(r0s + 8) * 132 + col] = make_float2(c[n][2] + b0, c[n][3] + b1);
        }
    }
    __syncthreads();

    if (MODE != 2) {
#pragma unroll
        for (int it = 0; it < 4; it++) {
            int r = it * 32 + (tid >> 3);
            int grow = row0 + r;
            if (grow < NN) {
                float* cp = C + (size_t)grow * HH;
#pragma unroll
                for (int j = 0; j < 4; j++) {
                    int c4 = (tid & 7) + j * 8;
                    *(float4*)(cp + c4 * 4) = *(float4*)&sm[r * 132 + c4 * 4];
                }
            }
        }
    } else {
        if (tid < 128) {
            int grow = row0 + tid;
            if (grow < NN) {
                float* hp = C + (size_t)grow * HH;
                float s = 0.f, sq = 0.f;
#pragma unroll
                for (int j = 0; j < 32; j++) {
                    float4 o = *(float4*)&sm[tid * 132 + j * 4];
                    float4 hv = *(float4*)(hp + j * 4);
                    float t0 = hv.x + fmaxf(o.x, 0.f);
                    float t1 = hv.y + fmaxf(o.y, 0.f);
                    float t2 = hv.z + fmaxf(o.z, 0.f);
                    float t3 = hv.w + fmaxf(o.w, 0.f);
                    s += t0 + t1 + t2 + t3;
                    sq += t0 * t0 + t1 * t1 + t2 * t2 + t3 * t3;
                }
                float mean = s * (1.0f / 128.0f);
                float var = sq * (1.0f / 128.0f) - mean * mean;
                float rr = rsqrtf(var + 1e-5f);
#pragma unroll
                for (int j = 0; j < 32; j++) {
                    float4 o = *(float4*)&sm[tid * 132 + j * 4];
                    float4 hv = *(float4*)(hp + j * 4);
                    float4 lg = *(float4*)&sm[F_LNG + j * 4];
                    float4 lb = *(float4*)&sm[F_LNB + j * 4];
                    float4 w;
                    w.x = (hv.x + fmaxf(o.x, 0.f) - mean) * rr * lg.x + lb.x;
                    w.y = (hv.y + fmaxf(o.y, 0.f) - mean) * rr * lg.y + lb.y;
                    w.z = (hv.z + fmaxf(o.z, 0.f) - mean) * rr * lg.z + lb.z;
                    w.w = (hv.w + fmaxf(o.w, 0.f) - mean) * rr * lg.w + lb.w;
                    *(float4*)(hp + j * 4) = w;
                }
            }
        }
    }
}

// ================== fused aggregation + GEMM-1 (full-K, BN stats) ==================
// smem bytes: Ahi@0 Alo@32768 Bhi@65536 Blo@98304 (each 32 KB), bias fp32 @131072.
// Epilogue re-uses [0 .. 67584) as fp32 staging [128][132].
constexpr int SMEM_AG = 131072 + 512;           // 131584 B
constexpr int FAG_BIAS = 32768;                  // float index of bias

__global__ void __launch_bounds__(256, 1) agg_gemm(
    const float* __restrict__ H, const u16* __restrict__ Whi, const u16* __restrict__ Wlo,
    const float* __restrict__ bias, float* __restrict__ Cz,
    const float* __restrict__ eps_l, int layer)
{
    extern __shared__ float sm[];
    const u32 sb = smem_u32(sm);
    const int tid = threadIdx.x;
    const int lane = tid & 31, wid = tid >> 5;
    const int row0 = blockIdx.x * 128;

    if (tid < 128) sm[FAG_BIAS + tid] = __ldg(bias + tid);

    // ---- B tiles: full K=128, 128n x 128k bf16 hi/lo, swizzled ----
#pragma unroll
    for (int i = 0; i < 8; i++) {
        int f = i * 256 + tid;            // 2048 uint4
        int n = f >> 4, q = f & 15;
        uint4 vh = __ldg((const uint4*)(Whi + (size_t)n * HH) + q);
        uint4 vl = __ldg((const uint4*)(Wlo + (size_t)n * HH) + q);
        u32 off = (u32)(n * 256 + ((q ^ (n & 7)) << 4));
        *(uint4*)((char*)sm + 65536 + off) = vh;
        *(uint4*)((char*)sm + 98304 + off) = vl;
    }

    // ---- gather u = (1+eps)h + sum_nbr h, one warp per node, split bf16 into A tiles ----
    const float e1 = 1.0f + __ldg(eps_l + layer);
    const float4* hp = (const float4*)H;
#pragma unroll 1
    for (int i = 0; i < 16; i++) {
        int r = wid * 16 + i;
        int node = row0 + r;
        float4 acc = make_float4(0.f, 0.f, 0.f, 0.f);
        if (node < NN) {
            float4 a = __ldg(hp + (size_t)node * 32 + lane);
            acc = make_float4(a.x * e1, a.y * e1, a.z * e1, a.w * e1);
            int beg = g_rowptr[node], end = g_rowptr[node + 1];
            int e = beg;
            for (; e + 4 <= end; e += 4) {
                int n0 = g_colidx[e], n1 = g_colidx[e + 1];
                int n2 = g_colidx[e + 2], n3 = g_colidx[e + 3];
                float4 v0 = __ldg(hp + (size_t)n0 * 32 + lane);
                float4 v1 = __ldg(hp + (size_t)n1 * 32 + lane);
                float4 v2 = __ldg(hp + (size_t)n2 * 32 + lane);
                float4 v3 = __ldg(hp + (size_t)n3 * 32 + lane);
                acc.x += (v0.x + v1.x) + (v2.x + v3.x);
                acc.y += (v0.y + v1.y) + (v2.y + v3.y);
                acc.z += (v0.z + v1.z) + (v2.z + v3.z);
                acc.w += (v0.w + v1.w) + (v2.w + v3.w);
            }
            for (; e < end; e++) {
                int nb = g_colidx[e];
                float4 v = __ldg(hp + (size_t)nb * 32 + lane);
                acc.x += v.x; acc.y += v.y; acc.z += v.z; acc.w += v.w;
            }
        }
        float hx = __bfloat162float(__float2bfloat16_rn(acc.x));
        float hy = __bfloat162float(__float2bfloat16_rn(acc.y));
        float hz = __bfloat162float(__float2bfloat16_rn(acc.z));
        float hw = __bfloat162float(__float2bfloat16_rn(acc.w));
        u32 off = (u32)(r * 256 + (((lane >> 1) ^ (r & 7)) << 4) + (lane & 1) * 8);
        *(uint2*)((char*)sm + off) = make_uint2(packbf2(acc.x, acc.y), packbf2(acc.z, acc.w));
        *(uint2*)((char*)sm + 32768 + off) =
            make_uint2(packbf2(acc.x - hx, acc.y - hy), packbf2(acc.z - hz, acc.w - hw));
    }
    __syncthreads();

    // ---- mainloop: 8 k-steps of 16 over full K=128 ----
    float c[16][4];
#pragma unroll
    for (int n = 0; n < 16; n++)
#pragma unroll
        for (int j = 0; j < 4; j++) c[n][j] = 0.f;

    const int ar = (wid << 4) + (lane & 7) + (lane & 8);
    const int bq = ((lane >> 4) << 3) + (lane & 7);
#pragma unroll
    for (int s = 0; s < 8; s++) {
        int ach = 2 * s + (lane >> 4);
        u32 aoff = (u32)(ar * 256 + ((ach ^ (ar & 7)) << 4));
        u32 ah[4], al[4];
        ldm4(ah, sb + aoff);
        ldm4(al, sb + 32768 + aoff);
        int bch = 2 * s + ((lane >> 3) & 1);
#pragma unroll
        for (int n2 = 0; n2 < 8; n2++) {
            int bn = (n2 << 4) + bq;
            u32 boff = (u32)(bn * 256 + ((bch ^ (bn & 7)) << 4));
            u32 bh[4], bl[4];
            ldm4(bh, sb + 65536 + boff);
            ldm4(bl, sb + 98304 + boff);
            mma16816(c[2 * n2],     ah, bh[0], bh[1]);
            mma16816(c[2 * n2],     ah, bl[0], bl[1]);
            mma16816(c[2 * n2],     al, bh[0], bh[1]);
            mma16816(c[2 * n2 + 1], ah, bh[2], bh[3]);
            mma16816(c[2 * n2 + 1], ah, bl[2], bl[3]);
            mma16816(c[2 * n2 + 1], al, bh[2], bh[3]);
        }
    }
    __syncthreads();

    // ---- stage + bias, write z, column BN stats ----
    {
        const int r0s = (wid << 4) + (lane >> 2);
#pragma unroll
        for (int n = 0; n < 16; n++) {
            int col = n * 8 + (lane & 3) * 2;
            float b0 = sm[FAG_BIAS + col], b1 = sm[FAG_BIAS + col + 1];
            *(float2*)&sm[r0s * 132 + col] = make_float2(c[n][0] + b0, c[n][1] + b1);
            *(float2*)&sm[(r0s + 8) * 132 + col] = make_float2(c[n][2] + b0, c[n][3] + b1);
        }
    }
    __syncthreads();
#pragma unroll
    for (int it = 0; it < 4; it++) {
        int r = it * 32 + (tid >> 3);
        int grow = row0 + r;
        if (grow < NN) {
            float* cp = Cz + (size_t)grow * HH;
#pragma unroll
            for (int j = 0; j < 4; j++) {
                int c4 = (tid & 7) + j * 8;
                *(float4*)(cp + c4 * 4) = *(float4*)&sm[r * 132 + c4 * 4];
            }
        }
    }
    if (tid < 128) {
        float s = 0.f, sq = 0.f;
        int rmax = NN - row0; if (rmax > 128) rmax = 128;
        for (int r = 0; r < rmax; r++) {
            float v = sm[r * 132 + tid];
            s += v; sq += v * v;
        }
        atomicAdd(&g_colsum[tid], s);
        atomicAdd(&g_colsq[tid], sq);
    }
}

// ------------------ weight transpose + bf16 split ------------------
__global__ void transposek(const float* __restrict__ W0, const float* __restrict__ W1,
                           const float* __restrict__ W2) {
    int i = blockIdx.x * 256 + threadIdx.x;
    if (i >= 9 * HH * HH) return;
    int s = i >> 14, r = i & 16383;
    int n = r >> 7, k = r & 127;
    const float* src = (s == 0) ? W0 : (s < 5 ? W1 + (s - 1) * HH * HH : W2 + (s - 5) * HH * HH);
    float x = __ldg(src + k * HH + n);
    __nv_bfloat16 hb = __float2bfloat16_rn(x);
    float hi = __bfloat162float(hb);
    __nv_bfloat16 lb = __float2bfloat16_rn(x - hi);
    g_wthi[i] = *(u16*)&hb;
    g_wtlo[i] = *(u16*)&lb;
}

// ------------------ graph preprocessing ------------------
__global__ void initk() {
    int i = blockIdx.x * blockDim.x + threadIdx.x;
    if (i < NN) g_deg[i] = 0;
    if (i < GG * HH) g_pool[i] = 0.f;
    if (i < GG) g_cnt[i] = 0.f;
    if (i < HH) { g_colsum[i] = 0.f; g_colsq[i] = 0.f; }
}

__global__ void degk(const int* __restrict__ ei) {
    int e = blockIdx.x * blockDim.x + threadIdx.x;
    if (e >= EE) return;
    int r = ei[e], c = ei[EE + e];
    if (r != c) { atomicAdd(&g_deg[r], 1); atomicAdd(&g_deg[c], 1); }
}

__global__ void scan1k() {
    int b = blockIdx.x, t = threadIdx.x;
    int i = b * 1024 + t;
    int lane = t & 31, wid = t >> 5;
    __shared__ int wsumS[32];
    int v = (i < NN) ? g_deg[i] : 0;
    int x = v;
#pragma unroll
    for (int d = 1; d < 32; d <<= 1) {
        int y = __shfl_up_sync(0xFFFFFFFFu, x, d);
        if (lane >= d) x += y;
    }
    if (lane == 31) wsumS[wid] = x;
    __syncthreads();
    if (wid == 0) {
        int w = wsumS[lane];
#pragma unroll
        for (int d = 1; d < 32; d <<= 1) {
            int y = __shfl_up_sync(0xFFFFFFFFu, w, d);
            if (lane >= d) w += y;
        }
        wsumS[lane] = w;
    }
    __syncthreads();
    int excl = (wid > 0 ? wsumS[wid - 1] : 0) + x - v;
    if (i < NN) g_rowptr[i] = excl;
    if (t == 1023) g_bsum[b] = excl + v;
}

__global__ void scan2k(int nblk) {
    int t = threadIdx.x;
    __shared__ int s[128];
    int v = (t < nblk) ? g_bsum[t] : 0;
    s[t] = v;
    __syncthreads();
    for (int d = 1; d < 128; d <<= 1) {
        int y = 0;
        if (t >= d) y = s[t - d];
        __syncthreads();
        if (t >= d) s[t] += y;
        __syncthreads();
    }
    g_boff[t] = s[t] - v;
    if (t == 127) g_rowptr[NN] = s[127];
}

__global__ void scan3k() {
    int i = blockIdx.x * 1024 + threadIdx.x;
    if (i < NN) {
        int r = g_rowptr[i] + g_boff[blockIdx.x];
        g_rowptr[i] = r;
        g_cur[i] = r;
    }
}

__global__ void fillk(const int* __restrict__ ei) {
    int e = blockIdx.x * blockDim.x + threadIdx.x;
    if (e >= EE) return;
    int r = ei[e], c = ei[EE + e];
    if (r != c) {
        int p = atomicAdd(&g_cur[r], 1); g_colidx[p] = c;
        int q = atomicAdd(&g_cur[c], 1); g_colidx[q] = r;
    }
}

// ------------------ BN parameter fold (and reset stats) ------------------
__global__ void bnparamsk(const float* __restrict__ bng, const float* __restrict__ bnb) {
    int f = threadIdx.x;
    float m = g_colsum[f] * (1.0f / NN);
    float v = g_colsq[f] * (1.0f / NN) - m * m;
    float sc = __ldg(bng + f) * rsqrtf(v + 1e-5f);
    g_bnscale[f] = sc;
    g_bnshift[f] = __ldg(bnb + f) - m * sc;
    g_colsum[f] = 0.f;
    g_colsq[f] = 0.f;
}

// ------------------ pooling (batch is sorted) ------------------
__global__ void poolk(const float* __restrict__ h, const int* __restrict__ batch) {
    int f = threadIdx.x;
    int chunk = (NN + gridDim.x - 1) / gridDim.x;
    int s = blockIdx.x * chunk;
    int e = s + chunk; if (e > NN) e = NN;
    if (s >= e) return;
    int g = __ldg(batch + s);
    float acc = 0.f, cnt = 0.f;
    for (int n = s; n < e; n++) {
        int bg = __ldg(batch + n);
        if (bg != g) {
            atomicAdd(&g_pool[g * HH + f], acc);
            if (f == 0) atomicAdd(&g_cnt[g], cnt);
            acc = 0.f; cnt = 0.f; g = bg;
        }
        acc += h[(size_t)n * HH + f];
        cnt += 1.f;
    }
    atomicAdd(&g_pool[g * HH + f], acc);
    if (f == 0) atomicAdd(&g_cnt[g], cnt);
}

__global__ void finalk(float* __restrict__ out) {
    int i = blockIdx.x * blockDim.x + threadIdx.x;
    if (i < GG * HH) {
        float c = g_cnt[i >> 7];
        out[i] = g_pool[i] / fmaxf(c, 1.0f);
    }
}

// ------------------ host launcher ------------------
extern "C" void kernel_launch(void* const* d_in, const int* in_sizes, int n_in,
                              void* d_out, int out_size) {
    const float* x     = (const float*)d_in[0];
    const float* W0    = (const float*)d_in[1];
    const float* b0    = (const float*)d_in[2];
    const float* eps_l = (const float*)d_in[3];
    const float* W1    = (const float*)d_in[4];
    const float* b1    = (const float*)d_in[5];
    const float* bng   = (const float*)d_in[6];
    const float* bnb   = (const float*)d_in[7];
    const float* W2    = (const float*)d_in[8];
    const float* b2    = (const float*)d_in[9];
    const float* lng   = (const float*)d_in[10];
    const float* lnb   = (const float*)d_in[11];
    const int*   ei    = (const int*)d_in[12];
    const int*   batch = (const int*)d_in[13];
    float* out = (float*)d_out;

    cudaFuncSetAttribute((const void*)gemm_hmma<0>, cudaFuncAttributeMaxDynamicSharedMemorySize, SMEM_HM);
    cudaFuncSetAttribute((const void*)gemm_hmma<2>, cudaFuncAttributeMaxDynamicSharedMemorySize, SMEM_HM);
    cudaFuncSetAttribute((const void*)agg_gemm, cudaFuncAttributeMaxDynamicSharedMemorySize, SMEM_AG);

    float *ph, *pz;
    u16 *pwh, *pwl;
    cudaGetSymbolAddress((void**)&ph, g_h);
    cudaGetSymbolAddress((void**)&pz, g_z);
    cudaGetSymbolAddress((void**)&pwh, g_wthi);
    cudaGetSymbolAddress((void**)&pwl, g_wtlo);

    const int NB = (NN + 1023) / 1024;   // 98
    const int GB = (NN + 127) / 128;     // 782

    initk<<<(NN + 255) / 256, 256>>>();
    transposek<<<(9 * HH * HH + 255) / 256, 256>>>(W0, W1, W2);
    degk<<<(EE + 255) / 256, 256>>>(ei);
    scan1k<<<NB, 1024>>>();
    scan2k<<<1, 128>>>(NB);
    scan3k<<<NB, 1024>>>();
    fillk<<<(EE + 255) / 256, 256>>>(ei);

    gemm_hmma<0><<<GB, 256, SMEM_HM>>>(x, pwh, pwl, b0, ph, nullptr, nullptr);

    for (int i = 0; i < LL; i++) {
        agg_gemm<<<GB, 256, SMEM_AG>>>(ph, pwh + (1 + i) * HH * HH, pwl + (1 + i) * HH * HH,
                                       b1 + i * HH, pz, eps_l, i);
        bnparamsk<<<1, 128>>>(bng + i * HH, bnb + i * HH);
        gemm_hmma<2><<<GB, 256, SMEM_HM>>>(pz, pwh + (5 + i) * HH * HH, pwl + (5 + i) * HH * HH,
                                           b2 + i * HH, ph, lng + i * HH, lnb + i * HH);
    }

    poolk<<<500, 128>>>(ph, batch);
    finalk<<<(GG * HH + 255) / 256, 256>>>(out);
}

// round 6
// speedup vs baseline: 1.2899x; 1.2899x over previous
#include <cuda_runtime.h>
#include <cuda_bf16.h>

#define NN 100000
#define EE 800000
#define HH 128
#define GG 64
#define LL 4

typedef unsigned int u32;
typedef unsigned short u16;

// ------------------ static device scratch ------------------
__device__ float g_h[(size_t)NN * HH];
__device__ float g_z[(size_t)NN * HH];
__device__ int   g_deg[NN];
__device__ int   g_rowptr[NN + 1];
__device__ int   g_cur[NN];
__device__ int   g_colidx[2 * EE];
__device__ int   g_bsum[128];
__device__ int   g_boff[128];
__device__ float g_colsum[HH];
__device__ float g_colsq[HH];
__device__ __align__(16) float g_bnscale[HH];
__device__ __align__(16) float g_bnshift[HH];
__device__ float g_pool[GG * HH];
__device__ float g_cnt[GG];
__device__ __align__(16) u16 g_wthi[9 * HH * HH];  // transposed [n][k] bf16 hi
__device__ __align__(16) u16 g_wtlo[9 * HH * HH];  // bf16 lo residual

// ------------------ PTX helpers ------------------
__device__ __forceinline__ u32 smem_u32(const void* p) {
    u32 a;
    asm("{ .reg .u64 t; cvta.to.shared.u64 t, %1; cvt.u32.u64 %0, t; }" : "=r"(a) : "l"(p));
    return a;
}
__device__ __forceinline__ void ldm4(u32 r[4], u32 addr) {
    asm volatile("ldmatrix.sync.aligned.m8n8.x4.shared.b16 {%0,%1,%2,%3}, [%4];"
                 : "=r"(r[0]), "=r"(r[1]), "=r"(r[2]), "=r"(r[3]) : "r"(addr));
}
__device__ __forceinline__ void mma16816(float* c, const u32 a[4], u32 b0, u32 b1) {
    asm volatile(
        "mma.sync.aligned.m16n8k16.row.col.f32.bf16.bf16.f32 "
        "{%0,%1,%2,%3}, {%4,%5,%6,%7}, {%8,%9}, {%0,%1,%2,%3};"
        : "+f"(c[0]), "+f"(c[1]), "+f"(c[2]), "+f"(c[3])
        : "r"(a[0]), "r"(a[1]), "r"(a[2]), "r"(a[3]), "r"(b0), "r"(b1));
}
__device__ __forceinline__ u32 packbf2(float x, float y) {
    __nv_bfloat162 t = __floats2bfloat162_rn(x, y);
    return *(u32*)&t;
}

// ================== half-K GEMM (MODE 0 / MODE 2) — unchanged, proven 823us shape ==================
constexpr int SMEM_HM = 17280 * 4;   // 69120 B
constexpr int F_BIAS = 16896, F_LNG = 17024, F_LNB = 17152;

template <int MODE>
__global__ void __launch_bounds__(256, 2) gemm_hmma(
    const float* __restrict__ A, const u16* __restrict__ Whi, const u16* __restrict__ Wlo,
    const float* __restrict__ bias, float* __restrict__ C,
    const float* __restrict__ lng, const float* __restrict__ lnb)
{
    extern __shared__ float sm[];
    const u32 sb = smem_u32(sm);
    const int tid = threadIdx.x;
    const int lane = tid & 31, wid = tid >> 5;
    const int row0 = blockIdx.x * 128;

    if (tid < 128) {
        sm[F_BIAS + tid] = __ldg(bias + tid);
        if (MODE == 2) { sm[F_LNG + tid] = __ldg(lng + tid); sm[F_LNB + tid] = __ldg(lnb + tid); }
    }

    float c[16][4];
#pragma unroll
    for (int n = 0; n < 16; n++)
#pragma unroll
        for (int j = 0; j < 4; j++) c[n][j] = 0.f;

    for (int h = 0; h < 2; h++) {
#pragma unroll
        for (int i = 0; i < 4; i++) {
            int f = i * 256 + tid;
            int n = f >> 3, q = f & 7;
            uint4 vh = __ldg((const uint4*)(Whi + (size_t)n * HH + h * 64) + q);
            uint4 vl = __ldg((const uint4*)(Wlo + (size_t)n * HH + h * 64) + q);
            u32 off = (u32)(n * 128 + ((q ^ (n & 7)) << 4));
            *(uint4*)((char*)sm + 32768 + off) = vh;
            *(uint4*)((char*)sm + 49152 + off) = vl;
        }
#pragma unroll
        for (int i = 0; i < 8; i++) {
            int f = i * 256 + tid;
            int r = f >> 4, c4 = f & 15;
            int row = row0 + r;
            float4 v = make_float4(0.f, 0.f, 0.f, 0.f);
            if (row < NN) v = __ldg((const float4*)(A + (size_t)row * HH + h * 64) + c4);
            if (MODE == 2) {
                float4 sc = ((const float4*)g_bnscale)[h * 16 + c4];
                float4 sh = ((const float4*)g_bnshift)[h * 16 + c4];
                v.x = fmaxf(fmaf(v.x, sc.x, sh.x), 0.f);
                v.y = fmaxf(fmaf(v.y, sc.y, sh.y), 0.f);
                v.z = fmaxf(fmaf(v.z, sc.z, sh.z), 0.f);
                v.w = fmaxf(fmaf(v.w, sc.w, sh.w), 0.f);
            }
            float hx = __bfloat162float(__float2bfloat16_rn(v.x));
            float hy = __bfloat162float(__float2bfloat16_rn(v.y));
            float hz = __bfloat162float(__float2bfloat16_rn(v.z));
            float hw = __bfloat162float(__float2bfloat16_rn(v.w));
            u32 off = (u32)(r * 128 + (((c4 >> 1) ^ (r & 7)) << 4) + (c4 & 1) * 8);
            *(uint2*)((char*)sm + off) = make_uint2(packbf2(v.x, v.y), packbf2(v.z, v.w));
            *(uint2*)((char*)sm + 16384 + off) =
                make_uint2(packbf2(v.x - hx, v.y - hy), packbf2(v.z - hz, v.w - hw));
        }
        __syncthreads();

        const int ar = (wid << 4) + (lane & 7) + (lane & 8);
        const int bq = ((lane >> 4) << 3) + (lane & 7);
#pragma unroll
        for (int s = 0; s < 4; s++) {
            int ach = 2 * s + (lane >> 4);
            u32 aoff = (u32)(ar * 128 + ((ach ^ (ar & 7)) << 4));
            u32 ah[4], al[4];
            ldm4(ah, sb + aoff);
            ldm4(al, sb + 16384 + aoff);
            int bch = 2 * s + ((lane >> 3) & 1);
#pragma unroll
            for (int n2 = 0; n2 < 8; n2++) {
                int bn = (n2 << 4) + bq;
                u32 boff = (u32)(bn * 128 + ((bch ^ (bn & 7)) << 4));
                u32 bh[4], bl[4];
                ldm4(bh, sb + 32768 + boff);
                ldm4(bl, sb + 49152 + boff);
                mma16816(c[2 * n2],     ah, bh[0], bh[1]);
                mma16816(c[2 * n2],     ah, bl[0], bl[1]);
                mma16816(c[2 * n2],     al, bh[0], bh[1]);
                mma16816(c[2 * n2 + 1], ah, bh[2], bh[3]);
                mma16816(c[2 * n2 + 1], ah, bl[2], bl[3]);
                mma16816(c[2 * n2 + 1], al, bh[2], bh[3]);
            }
        }
        __syncthreads();
    }

    {
        const int r0s = (wid << 4) + (lane >> 2);
#pragma unroll
        for (int n = 0; n < 16; n++) {
            int col = n * 8 + (lane & 3) * 2;
            float b0 = sm[F_BIAS + col], b1 = sm[F_BIAS + col + 1];
            *(float2*)&sm[r0s * 132 + col] = make_float2(c[n][0] + b0, c[n][1] + b1);
            *(float2*)&sm[(r0s + 8) * 132 + col] = make_float2(c[n][2] + b0, c[n][3] + b1);
        }
    }
    __syncthreads();

    if (MODE != 2) {
#pragma unroll
        for (int it = 0; it < 4; it++) {
            int r = it * 32 + (tid >> 3);
            int grow = row0 + r;
            if (grow < NN) {
                float* cp = C + (size_t)grow * HH;
#pragma unroll
                for (int j = 0; j < 4; j++) {
                    int c4 = (tid & 7) + j * 8;
                    *(float4*)(cp + c4 * 4) = *(float4*)&sm[r * 132 + c4 * 4];
                }
            }
        }
    } else {
        if (tid < 128) {
            int grow = row0 + tid;
            if (grow < NN) {
                float* hp = C + (size_t)grow * HH;
                float s = 0.f, sq = 0.f;
#pragma unroll
                for (int j = 0; j < 32; j++) {
                    float4 o = *(float4*)&sm[tid * 132 + j * 4];
                    float4 hv = *(float4*)(hp + j * 4);
                    float t0 = hv.x + fmaxf(o.x, 0.f);
                    float t1 = hv.y + fmaxf(o.y, 0.f);
                    float t2 = hv.z + fmaxf(o.z, 0.f);
                    float t3 = hv.w + fmaxf(o.w, 0.f);
                    s += t0 + t1 + t2 + t3;
                    sq += t0 * t0 + t1 * t1 + t2 * t2 + t3 * t3;
                }
                float mean = s * (1.0f / 128.0f);
                float var = sq * (1.0f / 128.0f) - mean * mean;
                float rr = rsqrtf(var + 1e-5f);
#pragma unroll
                for (int j = 0; j < 32; j++) {
                    float4 o = *(float4*)&sm[tid * 132 + j * 4];
                    float4 hv = *(float4*)(hp + j * 4);
                    float4 lg = *(float4*)&sm[F_LNG + j * 4];
                    float4 lb = *(float4*)&sm[F_LNB + j * 4];
                    float4 w;
                    w.x = (hv.x + fmaxf(o.x, 0.f) - mean) * rr * lg.x + lb.x;
                    w.y = (hv.y + fmaxf(o.y, 0.f) - mean) * rr * lg.y + lb.y;
                    w.z = (hv.z + fmaxf(o.z, 0.f) - mean) * rr * lg.z + lb.z;
                    w.w = (hv.w + fmaxf(o.w, 0.f) - mean) * rr * lg.w + lb.w;
                    *(float4*)(hp + j * 4) = w;
                }
            }
        }
    }
}

// ================== fused aggregation + GEMM-1 v2: 2 CTAs/SM, MLP-8 gather ==================
// smem bytes: Ahi@0 (32KB, full-K), Alo@32768 (32KB), Bh@65536 (16KB half-K),
// Bl@81920 (16KB), bias @98304 (512B). Epilogue staging reuses [0..67584).
constexpr int SMEM_AG = 98816;
constexpr int FAG_BIAS = 24576;   // float index of bias (98304/4)

__global__ void __launch_bounds__(256, 2) agg_gemm(
    const float* __restrict__ H, const u16* __restrict__ Whi, const u16* __restrict__ Wlo,
    const float* __restrict__ bias, float* __restrict__ Cz,
    const float* __restrict__ eps_l, int layer)
{
    extern __shared__ float sm[];
    const u32 sb = smem_u32(sm);
    const int tid = threadIdx.x;
    const int lane = tid & 31, wid = tid >> 5;
    const int row0 = blockIdx.x * 128;

    if (tid < 128) sm[FAG_BIAS + tid] = __ldg(bias + tid);

    // ---- gather u = (1+eps)h + sum_nbr h, one warp/node, MLP-8 unroll, split bf16 ----
    const float e1 = 1.0f + __ldg(eps_l + layer);
    const float4* hp = (const float4*)H;
#pragma unroll 1
    for (int i = 0; i < 16; i++) {
        int r = wid * 16 + i;
        int node = row0 + r;
        float4 acc = make_float4(0.f, 0.f, 0.f, 0.f);
        if (node < NN) {
            float4 a = __ldg(hp + (size_t)node * 32 + lane);
            acc = make_float4(a.x * e1, a.y * e1, a.z * e1, a.w * e1);
            int beg = g_rowptr[node], end = g_rowptr[node + 1];
            int e = beg;
            for (; e + 8 <= end; e += 8) {
                int idx[8];
#pragma unroll
                for (int t = 0; t < 8; t++) idx[t] = g_colidx[e + t];
                float4 v[8];
#pragma unroll
                for (int t = 0; t < 8; t++) v[t] = __ldg(hp + (size_t)idx[t] * 32 + lane);
#pragma unroll
                for (int t = 0; t < 8; t++) {
                    acc.x += v[t].x; acc.y += v[t].y; acc.z += v[t].z; acc.w += v[t].w;
                }
            }
            if (e + 4 <= end) {
                int idx[4];
#pragma unroll
                for (int t = 0; t < 4; t++) idx[t] = g_colidx[e + t];
                float4 v[4];
#pragma unroll
                for (int t = 0; t < 4; t++) v[t] = __ldg(hp + (size_t)idx[t] * 32 + lane);
#pragma unroll
                for (int t = 0; t < 4; t++) {
                    acc.x += v[t].x; acc.y += v[t].y; acc.z += v[t].z; acc.w += v[t].w;
                }
                e += 4;
            }
            for (; e < end; e++) {
                int nb = g_colidx[e];
                float4 v = __ldg(hp + (size_t)nb * 32 + lane);
                acc.x += v.x; acc.y += v.y; acc.z += v.z; acc.w += v.w;
            }
        }
        float hx = __bfloat162float(__float2bfloat16_rn(acc.x));
        float hy = __bfloat162float(__float2bfloat16_rn(acc.y));
        float hz = __bfloat162float(__float2bfloat16_rn(acc.z));
        float hw = __bfloat162float(__float2bfloat16_rn(acc.w));
        u32 off = (u32)(r * 256 + (((lane >> 1) ^ (r & 7)) << 4) + (lane & 1) * 8);
        *(uint2*)((char*)sm + off) = make_uint2(packbf2(acc.x, acc.y), packbf2(acc.z, acc.w));
        *(uint2*)((char*)sm + 32768 + off) =
            make_uint2(packbf2(acc.x - hx, acc.y - hy), packbf2(acc.z - hz, acc.w - hw));
    }

    // ---- mainloop: B loaded per K-half (16KB hi + 16KB lo), A full-K resident ----
    float c[16][4];
#pragma unroll
    for (int n = 0; n < 16; n++)
#pragma unroll
        for (int j = 0; j < 4; j++) c[n][j] = 0.f;

    const int ar = (wid << 4) + (lane & 7) + (lane & 8);
    const int bq = ((lane >> 4) << 3) + (lane & 7);

    for (int h = 0; h < 2; h++) {
        __syncthreads();   // h=0: gather done; h=1: previous half's B reads done
#pragma unroll
        for (int i = 0; i < 4; i++) {
            int f = i * 256 + tid;
            int n = f >> 3, q = f & 7;
            uint4 vh = __ldg((const uint4*)(Whi + (size_t)n * HH + h * 64) + q);
            uint4 vl = __ldg((const uint4*)(Wlo + (size_t)n * HH + h * 64) + q);
            u32 off = (u32)(n * 128 + ((q ^ (n & 7)) << 4));
            *(uint4*)((char*)sm + 65536 + off) = vh;
            *(uint4*)((char*)sm + 81920 + off) = vl;
        }
        __syncthreads();
#pragma unroll
        for (int s = 0; s < 4; s++) {
            int ach = h * 8 + 2 * s + (lane >> 4);
            u32 aoff = (u32)(ar * 256 + ((ach ^ (ar & 7)) << 4));
            u32 ah[4], al[4];
            ldm4(ah, sb + aoff);
            ldm4(al, sb + 32768 + aoff);
            int bch = 2 * s + ((lane >> 3) & 1);
#pragma unroll
            for (int n2 = 0; n2 < 8; n2++) {
                int bn = (n2 << 4) + bq;
                u32 boff = (u32)(bn * 128 + ((bch ^ (bn & 7)) << 4));
                u32 bh[4], bl[4];
                ldm4(bh, sb + 65536 + boff);
                ldm4(bl, sb + 81920 + boff);
                mma16816(c[2 * n2],     ah, bh[0], bh[1]);
                mma16816(c[2 * n2],     ah, bl[0], bl[1]);
                mma16816(c[2 * n2],     al, bh[0], bh[1]);
                mma16816(c[2 * n2 + 1], ah, bh[2], bh[3]);
                mma16816(c[2 * n2 + 1], ah, bl[2], bl[3]);
                mma16816(c[2 * n2 + 1], al, bh[2], bh[3]);
            }
        }
    }
    __syncthreads();

    // ---- stage + bias (reuses A region), write z, column BN stats ----
    {
        const int r0s = (wid << 4) + (lane >> 2);
#pragma unroll
        for (int n = 0; n < 16; n++) {
            int col = n * 8 + (lane & 3) * 2;
            float b0 = sm[FAG_BIAS + col], b1 = sm[FAG_BIAS + col + 1];
            *(float2*)&sm[r0s * 132 + col] = make_float2(c[n][0] + b0, c[n][1] + b1);
            *(float2*)&sm[(r0s + 8) * 132 + col] = make_float2(c[n][2] + b0, c[n][3] + b1);
        }
    }
    __syncthreads();
#pragma unroll
    for (int it = 0; it < 4; it++) {
        int r = it * 32 + (tid >> 3);
        int grow = row0 + r;
        if (grow < NN) {
            float* cp = Cz + (size_t)grow * HH;
#pragma unroll
            for (int j = 0; j < 4; j++) {
                int c4 = (tid & 7) + j * 8;
                *(float4*)(cp + c4 * 4) = *(float4*)&sm[r * 132 + c4 * 4];
            }
        }
    }
    if (tid < 128) {
        float s = 0.f, sq = 0.f;
        int rmax = NN - row0; if (rmax > 128) rmax = 128;
        for (int r = 0; r < rmax; r++) {
            float v = sm[r * 132 + tid];
            s += v; sq += v * v;
        }
        atomicAdd(&g_colsum[tid], s);
        atomicAdd(&g_colsq[tid], sq);
    }
}

// ------------------ weight transpose + bf16 split ------------------
__global__ void transposek(const float* __restrict__ W0, const float* __restrict__ W1,
                           const float* __restrict__ W2) {
    int i = blockIdx.x * 256 + threadIdx.x;
    if (i >= 9 * HH * HH) return;
    int s = i >> 14, r = i & 16383;
    int n = r >> 7, k = r & 127;
    const float* src = (s == 0) ? W0 : (s < 5 ? W1 + (s - 1) * HH * HH : W2 + (s - 5) * HH * HH);
    float x = __ldg(src + k * HH + n);
    __nv_bfloat16 hb = __float2bfloat16_rn(x);
    float hi = __bfloat162float(hb);
    __nv_bfloat16 lb = __float2bfloat16_rn(x - hi);
    g_wthi[i] = *(u16*)&hb;
    g_wtlo[i] = *(u16*)&lb;
}

// ------------------ graph preprocessing ------------------
__global__ void initk() {
    int i = blockIdx.x * blockDim.x + threadIdx.x;
    if (i < NN) g_deg[i] = 0;
    if (i < GG * HH) g_pool[i] = 0.f;
    if (i < GG) g_cnt[i] = 0.f;
    if (i < HH) { g_colsum[i] = 0.f; g_colsq[i] = 0.f; }
}

__global__ void degk(const int* __restrict__ ei) {
    int e = blockIdx.x * blockDim.x + threadIdx.x;
    if (e >= EE) return;
    int r = ei[e], c = ei[EE + e];
    if (r != c) { atomicAdd(&g_deg[r], 1); atomicAdd(&g_deg[c], 1); }
}

__global__ void scan1k() {
    int b = blockIdx.x, t = threadIdx.x;
    int i = b * 1024 + t;
    int lane = t & 31, wid = t >> 5;
    __shared__ int wsumS[32];
    int v = (i < NN) ? g_deg[i] : 0;
    int x = v;
#pragma unroll
    for (int d = 1; d < 32; d <<= 1) {
        int y = __shfl_up_sync(0xFFFFFFFFu, x, d);
        if (lane >= d) x += y;
    }
    if (lane == 31) wsumS[wid] = x;
    __syncthreads();
    if (wid == 0) {
        int w = wsumS[lane];
#pragma unroll
        for (int d = 1; d < 32; d <<= 1) {
            int y = __shfl_up_sync(0xFFFFFFFFu, w, d);
            if (lane >= d) w += y;
        }
        wsumS[lane] = w;
    }
    __syncthreads();
    int excl = (wid > 0 ? wsumS[wid - 1] : 0) + x - v;
    if (i < NN) g_rowptr[i] = excl;
    if (t == 1023) g_bsum[b] = excl + v;
}

__global__ void scan2k(int nblk) {
    int t = threadIdx.x;
    __shared__ int s[128];
    int v = (t < nblk) ? g_bsum[t] : 0;
    s[t] = v;
    __syncthreads();
    for (int d = 1; d < 128; d <<= 1) {
        int y = 0;
        if (t >= d) y = s[t - d];
        __syncthreads();
        if (t >= d) s[t] += y;
        __syncthreads();
    }
    g_boff[t] = s[t] - v;
    if (t == 127) g_rowptr[NN] = s[127];
}

__global__ void scan3k() {
    int i = blockIdx.x * 1024 + threadIdx.x;
    if (i < NN) {
        int r = g_rowptr[i] + g_boff[blockIdx.x];
        g_rowptr[i] = r;
        g_cur[i] = r;
    }
}

__global__ void fillk(const int* __restrict__ ei) {
    int e = blockIdx.x * blockDim.x + threadIdx.x;
    if (e >= EE) return;
    int r = ei[e], c = ei[EE + e];
    if (r != c) {
        int p = atomicAdd(&g_cur[r], 1); g_colidx[p] = c;
        int q = atomicAdd(&g_cur[c], 1); g_colidx[q] = r;
    }
}

// ------------------ BN parameter fold (and reset stats) ------------------
__global__ void bnparamsk(const float* __restrict__ bng, const float* __restrict__ bnb) {
    int f = threadIdx.x;
    float m = g_colsum[f] * (1.0f / NN);
    float v = g_colsq[f] * (1.0f / NN) - m * m;
    float sc = __ldg(bng + f) * rsqrtf(v + 1e-5f);
    g_bnscale[f] = sc;
    g_bnshift[f] = __ldg(bnb + f) - m * sc;
    g_colsum[f] = 0.f;
    g_colsq[f] = 0.f;
}

// ------------------ pooling (batch is sorted) ------------------
__global__ void poolk(const float* __restrict__ h, const int* __restrict__ batch) {
    int f = threadIdx.x;
    int chunk = (NN + gridDim.x - 1) / gridDim.x;
    int s = blockIdx.x * chunk;
    int e = s + chunk; if (e > NN) e = NN;
    if (s >= e) return;
    int g = __ldg(batch + s);
    float acc = 0.f, cnt = 0.f;
    for (int n = s; n < e; n++) {
        int bg = __ldg(batch + n);
        if (bg != g) {
            atomicAdd(&g_pool[g * HH + f], acc);
            if (f == 0) atomicAdd(&g_cnt[g], cnt);
            acc = 0.f; cnt = 0.f; g = bg;
        }
        acc += h[(size_t)n * HH + f];
        cnt += 1.f;
    }
    atomicAdd(&g_pool[g * HH + f], acc);
    if (f == 0) atomicAdd(&g_cnt[g], cnt);
}

__global__ void finalk(float* __restrict__ out) {
    int i = blockIdx.x * blockDim.x + threadIdx.x;
    if (i < GG * HH) {
        float c = g_cnt[i >> 7];
        out[i] = g_pool[i] / fmaxf(c, 1.0f);
    }
}

// ------------------ host launcher ------------------
extern "C" void kernel_launch(void* const* d_in, const int* in_sizes, int n_in,
                              void* d_out, int out_size) {
    const float* x     = (const float*)d_in[0];
    const float* W0    = (const float*)d_in[1];
    const float* b0    = (const float*)d_in[2];
    const float* eps_l = (const float*)d_in[3];
    const float* W1    = (const float*)d_in[4];
    const float* b1    = (const float*)d_in[5];
    const float* bng   = (const float*)d_in[6];
    const float* bnb   = (const float*)d_in[7];
    const float* W2    = (const float*)d_in[8];
    const float* b2    = (const float*)d_in[9];
    const float* lng   = (const float*)d_in[10];
    const float* lnb   = (const float*)d_in[11];
    const int*   ei    = (const int*)d_in[12];
    const int*   batch = (const int*)d_in[13];
    float* out = (float*)d_out;

    cudaFuncSetAttribute((const void*)gemm_hmma<0>, cudaFuncAttributeMaxDynamicSharedMemorySize, SMEM_HM);
    cudaFuncSetAttribute((const void*)gemm_hmma<2>, cudaFuncAttributeMaxDynamicSharedMemorySize, SMEM_HM);
    cudaFuncSetAttribute((const void*)agg_gemm, cudaFuncAttributeMaxDynamicSharedMemorySize, SMEM_AG);

    float *ph, *pz;
    u16 *pwh, *pwl;
    cudaGetSymbolAddress((void**)&ph, g_h);
    cudaGetSymbolAddress((void**)&pz, g_z);
    cudaGetSymbolAddress((void**)&pwh, g_wthi);
    cudaGetSymbolAddress((void**)&pwl, g_wtlo);

    const int NB = (NN + 1023) / 1024;   // 98
    const int GB = (NN + 127) / 128;     // 782

    initk<<<(NN + 255) / 256, 256>>>();
    transposek<<<(9 * HH * HH + 255) / 256, 256>>>(W0, W1, W2);
    degk<<<(EE + 255) / 256, 256>>>(ei);
    scan1k<<<NB, 1024>>>();
    scan2k<<<1, 128>>>(NB);
    scan3k<<<NB, 1024>>>();
    fillk<<<(EE + 255) / 256, 256>>>(ei);

    gemm_hmma<0><<<GB, 256, SMEM_HM>>>(x, pwh, pwl, b0, ph, nullptr, nullptr);

    for (int i = 0; i < LL; i++) {
        agg_gemm<<<GB, 256, SMEM_AG>>>(ph, pwh + (1 + i) * HH * HH, pwl + (1 + i) * HH * HH,
                                       b1 + i * HH, pz, eps_l, i);
        bnparamsk<<<1, 128>>>(bng + i * HH, bnb + i * HH);
        gemm_hmma<2><<<GB, 256, SMEM_HM>>>(pz, pwh + (5 + i) * HH * HH, pwl + (5 + i) * HH * HH,
                                           b2 + i * HH, ph, lng + i * HH, lnb + i * HH);
    }

    poolk<<<500, 128>>>(ph, batch);
    finalk<<<(GG * HH + 255) / 256, 256>>>(out);
}

// round 7
// speedup vs baseline: 1.5312x; 1.1870x over previous
#include <cuda_runtime.h>
#include <cuda_bf16.h>

#define NN 100000
#define EE 800000
#define HH 128
#define GG 64
#define LL 4

typedef unsigned int u32;
typedef unsigned short u16;

// ------------------ static device scratch ------------------
__device__ float g_h[(size_t)NN * HH];
__device__ float g_u[(size_t)NN * HH];
__device__ float g_z[(size_t)NN * HH];
__device__ int   g_deg[NN];
__device__ int   g_rowptr[NN + 1];
__device__ int   g_cur[NN];
__device__ int   g_colidx[2 * EE];
__device__ int   g_bsum[128];
__device__ int   g_boff[128];
__device__ float g_colsum[LL * HH];
__device__ float g_colsq[LL * HH];
__device__ float g_pool[GG * HH];
__device__ float g_cnt[GG];
__device__ __align__(16) u16 g_wthi[9 * HH * HH];  // transposed [n][k] bf16 hi
__device__ __align__(16) u16 g_wtlo[9 * HH * HH];  // bf16 lo residual

// ------------------ PTX helpers ------------------
__device__ __forceinline__ u32 smem_u32(const void* p) {
    u32 a;
    asm("{ .reg .u64 t; cvta.to.shared.u64 t, %1; cvt.u32.u64 %0, t; }" : "=r"(a) : "l"(p));
    return a;
}
__device__ __forceinline__ void ldm4(u32 r[4], u32 addr) {
    asm volatile("ldmatrix.sync.aligned.m8n8.x4.shared.b16 {%0,%1,%2,%3}, [%4];"
                 : "=r"(r[0]), "=r"(r[1]), "=r"(r[2]), "=r"(r[3]) : "r"(addr));
}
__device__ __forceinline__ void mma16816(float* c, const u32 a[4], u32 b0, u32 b1) {
    asm volatile(
        "mma.sync.aligned.m16n8k16.row.col.f32.bf16.bf16.f32 "
        "{%0,%1,%2,%3}, {%4,%5,%6,%7}, {%8,%9}, {%0,%1,%2,%3};"
        : "+f"(c[0]), "+f"(c[1]), "+f"(c[2]), "+f"(c[3])
        : "r"(a[0]), "r"(a[1]), "r"(a[2]), "r"(a[3]), "r"(b0), "r"(b1));
}
__device__ __forceinline__ u32 packbf2(float x, float y) {
    __nv_bfloat162 t = __floats2bfloat162_rn(x, y);
    return *(u32*)&t;
}

// smem floats: staging/tiles [0..16896), bias@16896, lng@17024, lnb@17152,
// bnscale@17280, bnshift@17408; total 17536 floats.
constexpr int SMEM_HM = 17536 * 4;   // 70144 B
constexpr int F_BIAS = 16896, F_LNG = 17024, F_LNB = 17152, F_SC = 17280, F_SH = 17408;

// ------------------ fused HMMA 3xbf16 GEMM: 128x128 per CTA ------------------
// MODE 0: C = A@W + b
// MODE 1: C = A@W + b, accumulate per-layer column stats
// MODE 2: fold BN params from stats; A' = relu(A*sc+sh); C = LayerNorm(C + relu(A'@W + b))
template <int MODE>
__global__ void __launch_bounds__(256, 2) gemm_hmma(
    const float* __restrict__ A, const u16* __restrict__ Whi, const u16* __restrict__ Wlo,
    const float* __restrict__ bias, float* __restrict__ C,
    const float* __restrict__ lng, const float* __restrict__ lnb,
    const float* __restrict__ bng, const float* __restrict__ bnb, int layer)
{
    extern __shared__ float sm[];
    const u32 sb = smem_u32(sm);
    const int tid = threadIdx.x;
    const int lane = tid & 31, wid = tid >> 5;
    const int row0 = blockIdx.x * 128;

    if (tid < 128) {
        sm[F_BIAS + tid] = __ldg(bias + tid);
        if (MODE == 2) {
            sm[F_LNG + tid] = __ldg(lng + tid);
            sm[F_LNB + tid] = __ldg(lnb + tid);
            // fold BN params from global stats (redundant per CTA, replaces bnparamsk)
            float m = g_colsum[layer * HH + tid] * (1.0f / NN);
            float v = g_colsq[layer * HH + tid] * (1.0f / NN) - m * m;
            float sc = __ldg(bng + tid) * rsqrtf(v + 1e-5f);
            sm[F_SC + tid] = sc;
            sm[F_SH + tid] = __ldg(bnb + tid) - m * sc;
        }
    }
    if (MODE == 2) __syncthreads();

    float c[16][4];
#pragma unroll
    for (int n = 0; n < 16; n++)
#pragma unroll
        for (int j = 0; j < 4; j++) c[n][j] = 0.f;

    for (int h = 0; h < 2; h++) {
#pragma unroll
        for (int i = 0; i < 4; i++) {
            int f = i * 256 + tid;
            int n = f >> 3, q = f & 7;
            uint4 vh = __ldg((const uint4*)(Whi + (size_t)n * HH + h * 64) + q);
            uint4 vl = __ldg((const uint4*)(Wlo + (size_t)n * HH + h * 64) + q);
            u32 off = (u32)(n * 128 + ((q ^ (n & 7)) << 4));
            *(uint4*)((char*)sm + 32768 + off) = vh;
            *(uint4*)((char*)sm + 49152 + off) = vl;
        }
#pragma unroll
        for (int i = 0; i < 8; i++) {
            int f = i * 256 + tid;
            int r = f >> 4, c4 = f & 15;
            int row = row0 + r;
            float4 v = make_float4(0.f, 0.f, 0.f, 0.f);
            if (row < NN) v = __ldg((const float4*)(A + (size_t)row * HH + h * 64) + c4);
            if (MODE == 2) {
                float4 sc = *(float4*)&sm[F_SC + h * 64 + c4 * 4];
                float4 sh = *(float4*)&sm[F_SH + h * 64 + c4 * 4];
                v.x = fmaxf(fmaf(v.x, sc.x, sh.x), 0.f);
                v.y = fmaxf(fmaf(v.y, sc.y, sh.y), 0.f);
                v.z = fmaxf(fmaf(v.z, sc.z, sh.z), 0.f);
                v.w = fmaxf(fmaf(v.w, sc.w, sh.w), 0.f);
            }
            float hx = __bfloat162float(__float2bfloat16_rn(v.x));
            float hy = __bfloat162float(__float2bfloat16_rn(v.y));
            float hz = __bfloat162float(__float2bfloat16_rn(v.z));
            float hw = __bfloat162float(__float2bfloat16_rn(v.w));
            u32 off = (u32)(r * 128 + (((c4 >> 1) ^ (r & 7)) << 4) + (c4 & 1) * 8);
            *(uint2*)((char*)sm + off) = make_uint2(packbf2(v.x, v.y), packbf2(v.z, v.w));
            *(uint2*)((char*)sm + 16384 + off) =
                make_uint2(packbf2(v.x - hx, v.y - hy), packbf2(v.z - hz, v.w - hw));
        }
        __syncthreads();

        const int ar = (wid << 4) + (lane & 7) + (lane & 8);
        const int bq = ((lane >> 4) << 3) + (lane & 7);
#pragma unroll
        for (int s = 0; s < 4; s++) {
            int ach = 2 * s + (lane >> 4);
            u32 aoff = (u32)(ar * 128 + ((ach ^ (ar & 7)) << 4));
            u32 ah[4], al[4];
            ldm4(ah, sb + aoff);
            ldm4(al, sb + 16384 + aoff);
            int bch = 2 * s + ((lane >> 3) & 1);
#pragma unroll
            for (int n2 = 0; n2 < 8; n2++) {
                int bn = (n2 << 4) + bq;
                u32 boff = (u32)(bn * 128 + ((bch ^ (bn & 7)) << 4));
                u32 bh[4], bl[4];
                ldm4(bh, sb + 32768 + boff);
                ldm4(bl, sb + 49152 + boff);
                mma16816(c[2 * n2],     ah, bh[0], bh[1]);
                mma16816(c[2 * n2],     ah, bl[0], bl[1]);
                mma16816(c[2 * n2],     al, bh[0], bh[1]);
                mma16816(c[2 * n2 + 1], ah, bh[2], bh[3]);
                mma16816(c[2 * n2 + 1], ah, bl[2], bl[3]);
                mma16816(c[2 * n2 + 1], al, bh[2], bh[3]);
            }
        }
        __syncthreads();
    }

    // ---- stage C + bias into smem [128][132] fp32 ----
    {
        const int r0s = (wid << 4) + (lane >> 2);
#pragma unroll
        for (int n = 0; n < 16; n++) {
            int col = n * 8 + (lane & 3) * 2;
            float b0 = sm[F_BIAS + col], b1 = sm[F_BIAS + col + 1];
            *(float2*)&sm[r0s * 132 + col] = make_float2(c[n][0] + b0, c[n][1] + b1);
            *(float2*)&sm[(r0s + 8) * 132 + col] = make_float2(c[n][2] + b0, c[n][3] + b1);
        }
    }
    __syncthreads();

    if (MODE != 2) {
#pragma unroll
        for (int it = 0; it < 4; it++) {
            int r = it * 32 + (tid >> 3);
            int grow = row0 + r;
            if (grow < NN) {
                float* cp = C + (size_t)grow * HH;
#pragma unroll
                for (int j = 0; j < 4; j++) {
                    int c4 = (tid & 7) + j * 8;
                    *(float4*)(cp + c4 * 4) = *(float4*)&sm[r * 132 + c4 * 4];
                }
            }
        }
        if (MODE == 1 && tid < 128) {
            float s = 0.f, sq = 0.f;
            int rmax = NN - row0; if (rmax > 128) rmax = 128;
            for (int r = 0; r < rmax; r++) {
                float v = sm[r * 132 + tid];
                s += v; sq += v * v;
            }
            atomicAdd(&g_colsum[layer * HH + tid], s);
            atomicAdd(&g_colsq[layer * HH + tid], sq);
        }
    } else {
        if (tid < 128) {
            int grow = row0 + tid;
            if (grow < NN) {
                float* hp = C + (size_t)grow * HH;
                float s = 0.f, sq = 0.f;
#pragma unroll
                for (int j = 0; j < 32; j++) {
                    float4 o = *(float4*)&sm[tid * 132 + j * 4];
                    float4 hv = *(float4*)(hp + j * 4);
                    float t0 = hv.x + fmaxf(o.x, 0.f);
                    float t1 = hv.y + fmaxf(o.y, 0.f);
                    float t2 = hv.z + fmaxf(o.z, 0.f);
                    float t3 = hv.w + fmaxf(o.w, 0.f);
                    s += t0 + t1 + t2 + t3;
                    sq += t0 * t0 + t1 * t1 + t2 * t2 + t3 * t3;
                }
                float mean = s * (1.0f / 128.0f);
                float var = sq * (1.0f / 128.0f) - mean * mean;
                float rr = rsqrtf(var + 1e-5f);
#pragma unroll
                for (int j = 0; j < 32; j++) {
                    float4 o = *(float4*)&sm[tid * 132 + j * 4];
                    float4 hv = *(float4*)(hp + j * 4);
                    float4 lg = *(float4*)&sm[F_LNG + j * 4];
                    float4 lb = *(float4*)&sm[F_LNB + j * 4];
                    float4 w;
                    w.x = (hv.x + fmaxf(o.x, 0.f) - mean) * rr * lg.x + lb.x;
                    w.y = (hv.y + fmaxf(o.y, 0.f) - mean) * rr * lg.y + lb.y;
                    w.z = (hv.z + fmaxf(o.z, 0.f) - mean) * rr * lg.z + lb.z;
                    w.w = (hv.w + fmaxf(o.w, 0.f) - mean) * rr * lg.w + lb.w;
                    *(float4*)(hp + j * 4) = w;
                }
            }
        }
    }
}

// ------------------ weight transpose + bf16 split ------------------
__global__ void transposek(const float* __restrict__ W0, const float* __restrict__ W1,
                           const float* __restrict__ W2) {
    int i = blockIdx.x * 256 + threadIdx.x;
    if (i >= 9 * HH * HH) return;
    int s = i >> 14, r = i & 16383;
    int n = r >> 7, k = r & 127;
    const float* src = (s == 0) ? W0 : (s < 5 ? W1 + (s - 1) * HH * HH : W2 + (s - 5) * HH * HH);
    float x = __ldg(src + k * HH + n);
    __nv_bfloat16 hb = __float2bfloat16_rn(x);
    float hi = __bfloat162float(hb);
    __nv_bfloat16 lb = __float2bfloat16_rn(x - hi);
    g_wthi[i] = *(u16*)&hb;
    g_wtlo[i] = *(u16*)&lb;
}

// ------------------ graph preprocessing ------------------
__global__ void degk(const int* __restrict__ ei) {
    int e = blockIdx.x * blockDim.x + threadIdx.x;
    if (e >= EE) return;
    int r = ei[e], c = ei[EE + e];
    if (r != c) { atomicAdd(&g_deg[r], 1); atomicAdd(&g_deg[c], 1); }
}

__global__ void scan1k() {
    int b = blockIdx.x, t = threadIdx.x;
    int i = b * 1024 + t;
    int lane = t & 31, wid = t >> 5;
    __shared__ int wsumS[32];
    int v = (i < NN) ? g_deg[i] : 0;
    int x = v;
#pragma unroll
    for (int d = 1; d < 32; d <<= 1) {
        int y = __shfl_up_sync(0xFFFFFFFFu, x, d);
        if (lane >= d) x += y;
    }
    if (lane == 31) wsumS[wid] = x;
    __syncthreads();
    if (wid == 0) {
        int w = wsumS[lane];
#pragma unroll
        for (int d = 1; d < 32; d <<= 1) {
            int y = __shfl_up_sync(0xFFFFFFFFu, w, d);
            if (lane >= d) w += y;
        }
        wsumS[lane] = w;
    }
    __syncthreads();
    int excl = (wid > 0 ? wsumS[wid - 1] : 0) + x - v;
    if (i < NN) g_rowptr[i] = excl;
    if (t == 1023) g_bsum[b] = excl + v;
}

__global__ void scan2k(int nblk) {
    int t = threadIdx.x;
    __shared__ int s[128];
    int v = (t < nblk) ? g_bsum[t] : 0;
    s[t] = v;
    __syncthreads();
    for (int d = 1; d < 128; d <<= 1) {
        int y = 0;
        if (t >= d) y = s[t - d];
        __syncthreads();
        if (t >= d) s[t] += y;
        __syncthreads();
    }
    g_boff[t] = s[t] - v;
    if (t == 127) g_rowptr[NN] = s[127];
}

__global__ void scan3k() {
    int i = blockIdx.x * 1024 + threadIdx.x;
    if (i < NN) {
        int r = g_rowptr[i] + g_boff[blockIdx.x];
        g_rowptr[i] = r;
        g_cur[i] = r;
    }
}

__global__ void fillk(const int* __restrict__ ei) {
    int e = blockIdx.x * blockDim.x + threadIdx.x;
    if (e >= EE) return;
    int r = ei[e], c = ei[EE + e];
    if (r != c) {
        int p = atomicAdd(&g_cur[r], 1); g_colidx[p] = c;
        int q = atomicAdd(&g_cur[c], 1); g_colidx[q] = r;
    }
}

// ------------------ GIN aggregation: one warp per node, MLP-8 ------------------
__global__ void aggk(const float* __restrict__ h, float* __restrict__ u,
                     const float* __restrict__ eps_l, int layer) {
    int w = (blockIdx.x * blockDim.x + threadIdx.x) >> 5;
    if (w >= NN) return;
    int lane = threadIdx.x & 31;
    float e1 = 1.0f + __ldg(eps_l + layer);
    const float4* hp = (const float4*)h;
    float4 a = __ldg(hp + (size_t)w * 32 + lane);
    float4 acc = make_float4(a.x * e1, a.y * e1, a.z * e1, a.w * e1);
    int beg = g_rowptr[w], end = g_rowptr[w + 1];
    int e = beg;
    for (; e + 8 <= end; e += 8) {
        int idx[8];
#pragma unroll
        for (int t = 0; t < 8; t++) idx[t] = g_colidx[e + t];
        float4 v[8];
#pragma unroll
        for (int t = 0; t < 8; t++) v[t] = __ldg(hp + (size_t)idx[t] * 32 + lane);
#pragma unroll
        for (int t = 0; t < 8; t++) {
            acc.x += v[t].x; acc.y += v[t].y; acc.z += v[t].z; acc.w += v[t].w;
        }
    }
    if (e + 4 <= end) {
        int idx[4];
#pragma unroll
        for (int t = 0; t < 4; t++) idx[t] = g_colidx[e + t];
        float4 v[4];
#pragma unroll
        for (int t = 0; t < 4; t++) v[t] = __ldg(hp + (size_t)idx[t] * 32 + lane);
#pragma unroll
        for (int t = 0; t < 4; t++) {
            acc.x += v[t].x; acc.y += v[t].y; acc.z += v[t].z; acc.w += v[t].w;
        }
        e += 4;
    }
    for (; e < end; e++) {
        int nb = g_colidx[e];
        float4 v = __ldg(hp + (size_t)nb * 32 + lane);
        acc.x += v.x; acc.y += v.y; acc.z += v.z; acc.w += v.w;
    }
    ((float4*)u)[(size_t)w * 32 + lane] = acc;
}

// ------------------ pooling (batch is sorted) ------------------
__global__ void poolk(const float* __restrict__ h, const int* __restrict__ batch) {
    int f = threadIdx.x;
    int chunk = (NN + gridDim.x - 1) / gridDim.x;
    int s = blockIdx.x * chunk;
    int e = s + chunk; if (e > NN) e = NN;
    if (s >= e) return;
    int g = __ldg(batch + s);
    float acc = 0.f, cnt = 0.f;
    for (int n = s; n < e; n++) {
        int bg = __ldg(batch + n);
        if (bg != g) {
            atomicAdd(&g_pool[g * HH + f], acc);
            if (f == 0) atomicAdd(&g_cnt[g], cnt);
            acc = 0.f; cnt = 0.f; g = bg;
        }
        acc += h[(size_t)n * HH + f];
        cnt += 1.f;
    }
    atomicAdd(&g_pool[g * HH + f], acc);
    if (f == 0) atomicAdd(&g_cnt[g], cnt);
}

__global__ void finalk(float* __restrict__ out) {
    int i = blockIdx.x * blockDim.x + threadIdx.x;
    if (i < GG * HH) {
        float c = g_cnt[i >> 7];
        out[i] = g_pool[i] / fmaxf(c, 1.0f);
    }
}

// ------------------ host launcher ------------------
extern "C" void kernel_launch(void* const* d_in, const int* in_sizes, int n_in,
                              void* d_out, int out_size) {
    const float* x     = (const float*)d_in[0];
    const float* W0    = (const float*)d_in[1];
    const float* b0    = (const float*)d_in[2];
    const float* eps_l = (const float*)d_in[3];
    const float* W1    = (const float*)d_in[4];
    const float* b1    = (const float*)d_in[5];
    const float* bng   = (const float*)d_in[6];
    const float* bnb   = (const float*)d_in[7];
    const float* W2    = (const float*)d_in[8];
    const float* b2    = (const float*)d_in[9];
    const float* lng   = (const float*)d_in[10];
    const float* lnb   = (const float*)d_in[11];
    const int*   ei    = (const int*)d_in[12];
    const int*   batch = (const int*)d_in[13];
    float* out = (float*)d_out;

    cudaFuncSetAttribute((const void*)gemm_hmma<0>, cudaFuncAttributeMaxDynamicSharedMemorySize, SMEM_HM);
    cudaFuncSetAttribute((const void*)gemm_hmma<1>, cudaFuncAttributeMaxDynamicSharedMemorySize, SMEM_HM);
    cudaFuncSetAttribute((const void*)gemm_hmma<2>, cudaFuncAttributeMaxDynamicSharedMemorySize, SMEM_HM);

    float *ph, *pu, *pz, *pcs, *pcq, *ppool, *pcnt;
    int *pdeg;
    u16 *pwh, *pwl;
    cudaGetSymbolAddress((void**)&ph, g_h);
    cudaGetSymbolAddress((void**)&pu, g_u);
    cudaGetSymbolAddress((void**)&pz, g_z);
    cudaGetSymbolAddress((void**)&pcs, g_colsum);
    cudaGetSymbolAddress((void**)&pcq, g_colsq);
    cudaGetSymbolAddress((void**)&ppool, g_pool);
    cudaGetSymbolAddress((void**)&pcnt, g_cnt);
    cudaGetSymbolAddress((void**)&pdeg, g_deg);
    cudaGetSymbolAddress((void**)&pwh, g_wthi);
    cudaGetSymbolAddress((void**)&pwl, g_wtlo);

    const int NB = (NN + 1023) / 1024;   // 98
    const int GB = (NN + 127) / 128;     // 782

    // memset nodes (not kernels)
    cudaMemsetAsync(pdeg, 0, NN * sizeof(int));
    cudaMemsetAsync(pcs, 0, LL * HH * sizeof(float));
    cudaMemsetAsync(pcq, 0, LL * HH * sizeof(float));
    cudaMemsetAsync(ppool, 0, GG * HH * sizeof(float));
    cudaMemsetAsync(pcnt, 0, GG * sizeof(float));

    transposek<<<(9 * HH * HH + 255) / 256, 256>>>(W0, W1, W2);        // launch 1
    degk<<<(EE + 255) / 256, 256>>>(ei);                               // 2
    scan1k<<<NB, 1024>>>();                                            // 3
    scan2k<<<1, 128>>>(NB);                                            // 4
    scan3k<<<NB, 1024>>>();                                            // 5
    gemm_hmma<0><<<GB, 256, SMEM_HM>>>(x, pwh, pwl, b0, ph,
                                       nullptr, nullptr, nullptr, nullptr, 0);  // 6 <- ncu
    fillk<<<(EE + 255) / 256, 256>>>(ei);                              // 7

    for (int i = 0; i < LL; i++) {
        aggk<<<(NN * 32 + 255) / 256, 256>>>(ph, pu, eps_l, i);
        gemm_hmma<1><<<GB, 256, SMEM_HM>>>(pu, pwh + (1 + i) * HH * HH, pwl + (1 + i) * HH * HH,
                                           b1 + i * HH, pz, nullptr, nullptr, nullptr, nullptr, i);
        gemm_hmma<2><<<GB, 256, SMEM_HM>>>(pz, pwh + (5 + i) * HH * HH, pwl + (5 + i) * HH * HH,
                                           b2 + i * HH, ph, lng + i * HH, lnb + i * HH,
                                           bng + i * HH, bnb + i * HH, i);
    }

    poolk<<<1000, 128>>>(ph, batch);
    finalk<<<(GG * HH + 255) / 256, 256>>>(out);
}